// round 1
// baseline (speedup 1.0000x reference)
#include <cuda_runtime.h>
#include <math.h>

// Problem constants
#define Bb    2
#define Ll    8192
#define DMm   256
#define NHh   4
#define HPp   64
#define NSs   8
#define DPROJ 532          // 2*DIN + 2*NS + NH
#define ZXW   1064         // 2*DPROJ
#define ZXS   1088         // padded row stride for zx scratch
#define Mrows (Bb*Ll)      // 16384
#define LC    64           // scan chunk length
#define NCc   (Ll/LC)      // 128 chunks

// ---------------- scratch (static device memory; no allocations) -------------
__device__ __align__(16) float g_zxH[(size_t)Mrows * ZXS];
__device__ __align__(16) float g_zxV[(size_t)Mrows * ZXS];
__device__ __align__(16) float g_E  [(size_t)4 * Bb * NHh * NCc * HPp * NSs];
__device__ __align__(16) float g_S0 [(size_t)4 * Bb * NHh * NCc * HPp * NSs];
__device__ __align__(16) float g_P  [4 * Bb * NHh * NCc];
__device__ __align__(16) float g_ydir[(size_t)4 * Bb * Ll * DMm];
__device__ __align__(16) float g_cat [(size_t)Mrows * 1024];
__device__ float g_dtb[4][NHh];
__device__ float g_Aco[4][NHh];
__device__ float g_Dv [4][NHh];

// ---------------- helpers ----------------------------------------------------
__device__ __forceinline__ float siluf(float x) { return x / (1.0f + expf(-x)); }
__device__ __forceinline__ float softplusf(float x) {
    return (x > 20.0f) ? x : log1pf(expf(x));
}

struct PtrPack { const float* q[12]; };  // dtb[4], A_log[4], D[4]

__global__ void k_prep(PtrPack pp) {
    int i = threadIdx.x;
    if (i < 16) {
        int d = i >> 2, h = i & 3;
        g_dtb[d][h] = pp.q[d][h];
        g_Aco[d][h] = -expf(pp.q[4 + d][h]);
        g_Dv [d][h] = pp.q[8 + d][h];
    }
}

// ---------------- generic fp32 SGEMM: C[M,*] = op(A)[M,K] @ W[K,Nw] ----------
// 128x128 tile, BK=16, 256 threads, 8x8 microtile. Column guards: Nw for W
// loads (zero-fill), Nstore for C stores. siluA applies silu to A on load.
__global__ __launch_bounds__(256) void k_sgemm(
    const float* __restrict__ A, int lda,
    const float* __restrict__ W, int ldw, int Nw,
    float* __restrict__ C, int ldc, int Nstore,
    int K, int siluA)
{
    __shared__ float As[16][128];
    __shared__ float Ws[16][128];
    const int tid = threadIdx.x;
    const int m0 = blockIdx.y * 128;
    const int n0 = blockIdx.x * 128;
    const int tm = (tid >> 4) << 3;
    const int tn = (tid & 15) << 3;

    float acc[8][8];
#pragma unroll
    for (int i = 0; i < 8; i++)
#pragma unroll
        for (int j = 0; j < 8; j++) acc[i][j] = 0.0f;

    for (int k0 = 0; k0 < K; k0 += 16) {
#pragma unroll
        for (int it = 0; it < 2; ++it) {
            int idx = tid + (it << 8);
            int row = idx >> 2;
            int kk  = (idx & 3) << 2;
            float4 av = *(const float4*)(A + (size_t)(m0 + row) * lda + k0 + kk);
            if (siluA) {
                av.x = siluf(av.x); av.y = siluf(av.y);
                av.z = siluf(av.z); av.w = siluf(av.w);
            }
            As[kk + 0][row] = av.x; As[kk + 1][row] = av.y;
            As[kk + 2][row] = av.z; As[kk + 3][row] = av.w;
        }
#pragma unroll
        for (int it = 0; it < 2; ++it) {
            int idx = tid + (it << 8);
            int kk  = idx >> 5;
            int nc  = (idx & 31) << 2;
            int gc  = n0 + nc;
            float4 wv = make_float4(0.f, 0.f, 0.f, 0.f);
            if (gc < Nw)  // Nw and gc are multiples of 4 -> whole float4 valid
                wv = *(const float4*)(W + (size_t)(k0 + kk) * ldw + gc);
            *(float4*)&Ws[kk][nc] = wv;
        }
        __syncthreads();
#pragma unroll
        for (int kk = 0; kk < 16; kk++) {
            float4 a0 = *(const float4*)&As[kk][tm];
            float4 a1 = *(const float4*)&As[kk][tm + 4];
            float4 b0 = *(const float4*)&Ws[kk][tn];
            float4 b1 = *(const float4*)&Ws[kk][tn + 4];
            float av[8] = {a0.x, a0.y, a0.z, a0.w, a1.x, a1.y, a1.z, a1.w};
            float bv[8] = {b0.x, b0.y, b0.z, b0.w, b1.x, b1.y, b1.z, b1.w};
#pragma unroll
            for (int i = 0; i < 8; i++)
#pragma unroll
                for (int j = 0; j < 8; j++)
                    acc[i][j] = fmaf(av[i], bv[j], acc[i][j]);
        }
        __syncthreads();
    }
#pragma unroll
    for (int i = 0; i < 8; i++) {
        int row = m0 + tm + i;
#pragma unroll
        for (int j = 0; j < 8; j += 4) {
            int col = n0 + tn + j;
            if (col < Nstore) {
                float4 v = make_float4(acc[i][j], acc[i][j + 1],
                                       acc[i][j + 2], acc[i][j + 3]);
                *(float4*)(C + (size_t)row * ldc + col) = v;
            }
        }
    }
}

// ---------------- scan pass 1: per-chunk local scan from zero state ----------
// grid: (NCc, Bb*NHh, 4 dirs), block: 64 threads (p index).
__global__ __launch_bounds__(64) void k_scan1() {
    const int c  = blockIdx.x;
    const int b  = blockIdx.y >> 2;
    const int h  = blockIdx.y & 3;
    const int d  = blockIdx.z;
    const int p  = threadIdx.x;
    const float* zx = (d < 2) ? g_zxH : g_zxV;
    const int off = (d & 1) * DPROJ;
    const int rev = d & 1;

    __shared__ float sa[LC];
    __shared__ float sdtB[LC][NSs];
    __shared__ float sx[LC][HPp];

    {   // per-step scalars: thread j handles step j
        int i = p;
        int t = rev ? (Ll - 1 - (c * LC + i)) : (c * LC + i);
        const float* row = zx + (size_t)(b * Ll + t) * ZXS + off;
        float dt = softplusf(row[528 + h] + g_dtb[d][h]);
        sa[i] = expf(dt * g_Aco[d][h]);
#pragma unroll
        for (int n = 0; n < NSs; n++) sdtB[i][n] = dt * siluf(row[512 + n]);
    }
#pragma unroll 8
    for (int i = 0; i < LC; i++) {
        int t = rev ? (Ll - 1 - (c * LC + i)) : (c * LC + i);
        sx[i][p] = siluf(zx[(size_t)(b * Ll + t) * ZXS + off + 256 + h * HPp + p]);
    }
    __syncthreads();

    float s[NSs];
#pragma unroll
    for (int n = 0; n < NSs; n++) s[n] = 0.0f;
    float pr = 1.0f;
#pragma unroll 4
    for (int i = 0; i < LC; i++) {
        float a = sa[i];
        float xv = sx[i][p];
        pr *= a;
#pragma unroll
        for (int n = 0; n < NSs; n++) s[n] = fmaf(a, s[n], sdtB[i][n] * xv);
    }
    size_t base = ((((size_t)d * Bb + b) * NHh + h) * NCc + c);
    float* Ep = g_E + base * HPp * NSs + p * NSs;
#pragma unroll
    for (int n = 0; n < NSs; n++) Ep[n] = s[n];
    if (p == 0) g_P[base] = pr;
}

// ---------------- scan pass 2: combine chunk summaries (sequential in c) -----
__global__ __launch_bounds__(64) void k_scan2() {
    const int bid = blockIdx.x;      // 32 blocks: d*8 + b*4 + h
    const int d = bid >> 3, b = (bid >> 2) & 1, h = bid & 3;
    const int p = threadIdx.x;
    size_t base = (((size_t)d * Bb + b) * NHh + h) * NCc;
    float s[NSs];
#pragma unroll
    for (int n = 0; n < NSs; n++) s[n] = 0.0f;
    for (int c = 0; c < NCc; c++) {
        float* S0p = g_S0 + (base + c) * HPp * NSs + p * NSs;
        const float* Ep = g_E + (base + c) * HPp * NSs + p * NSs;
        float P = g_P[base + c];
#pragma unroll
        for (int n = 0; n < NSs; n++) {
            S0p[n] = s[n];
            s[n] = fmaf(P, s[n], Ep[n]);
        }
    }
}

// ---------------- scan pass 3: replay with true init state, emit y -----------
__global__ __launch_bounds__(64) void k_scan3(const int* __restrict__ v2h) {
    const int c  = blockIdx.x;
    const int b  = blockIdx.y >> 2;
    const int h  = blockIdx.y & 3;
    const int d  = blockIdx.z;
    const int p  = threadIdx.x;
    const float* zx = (d < 2) ? g_zxH : g_zxV;
    const int off = (d & 1) * DPROJ;
    const int rev = d & 1;

    __shared__ float sa[LC];
    __shared__ float sdtB[LC][NSs];
    __shared__ float sC[LC][NSs];
    __shared__ float sx[LC][HPp];
    __shared__ float sz[LC][HPp];

    {
        int i = p;
        int t = rev ? (Ll - 1 - (c * LC + i)) : (c * LC + i);
        const float* row = zx + (size_t)(b * Ll + t) * ZXS + off;
        float dt = softplusf(row[528 + h] + g_dtb[d][h]);
        sa[i] = expf(dt * g_Aco[d][h]);
#pragma unroll
        for (int n = 0; n < NSs; n++) {
            sdtB[i][n] = dt * siluf(row[512 + n]);
            sC[i][n]   = siluf(row[520 + n]);
        }
    }
#pragma unroll 8
    for (int i = 0; i < LC; i++) {
        int t = rev ? (Ll - 1 - (c * LC + i)) : (c * LC + i);
        const float* row = zx + (size_t)(b * Ll + t) * ZXS + off;
        sx[i][p] = siluf(row[256 + h * HPp + p]);
        sz[i][p] = row[h * HPp + p];
    }
    __syncthreads();

    size_t base = ((((size_t)d * Bb + b) * NHh + h) * NCc + c);
    const float* S0p = g_S0 + base * HPp * NSs + p * NSs;
    float s[NSs];
#pragma unroll
    for (int n = 0; n < NSs; n++) s[n] = S0p[n];
    const float Dh = g_Dv[d][h];
    const size_t ybase = (((size_t)d * Bb + b) * Ll);

    for (int i = 0; i < LC; i++) {
        int t = rev ? (Ll - 1 - (c * LC + i)) : (c * LC + i);
        float a = sa[i];
        float xv = sx[i][p];
#pragma unroll
        for (int n = 0; n < NSs; n++) s[n] = fmaf(a, s[n], sdtB[i][n] * xv);
        float y = 0.0f;
#pragma unroll
        for (int n = 0; n < NSs; n++) y = fmaf(s[n], sC[i][n], y);
        float out = (y + Dh * xv) * siluf(sz[i][p]);
        int trow = (d >= 2) ? v2h[b * Ll + t] : t;
        g_ydir[(ybase + trow) * DMm + h * HPp + p] = out;
    }
}

// ---------------- launch -----------------------------------------------------
extern "C" void kernel_launch(void* const* d_in, const int* in_sizes, int n_in,
                              void* d_out, int out_size) {
    const float *xH, *xV, *WinH, *WinV, *WoHF, *WoHB, *WoVF, *WoVB, *Wout;
    const float *dtb[4], *alog[4], *Dp[4];
    const int* v2h;

    if (in_sizes[4] > 1000) {
        // dict (setup_inputs insertion) order
        xH   = (const float*)d_in[0];  xV   = (const float*)d_in[1];
        WinH = (const float*)d_in[2];  WinV = (const float*)d_in[3];
        WoHF = (const float*)d_in[4];  WoHB = (const float*)d_in[5];
        WoVF = (const float*)d_in[6];  WoVB = (const float*)d_in[7];
        Wout = (const float*)d_in[8];
        for (int d = 0; d < 4; d++) {
            dtb[d]  = (const float*)d_in[9 + 3 * d];
            alog[d] = (const float*)d_in[10 + 3 * d];
            Dp[d]   = (const float*)d_in[11 + 3 * d];
        }
        v2h = (const int*)d_in[21];
    } else {
        // reference-signature order
        xH   = (const float*)d_in[0];  xV   = (const float*)d_in[1];
        WinH = (const float*)d_in[2];  WinV = (const float*)d_in[3];
        for (int d = 0; d < 4; d++) {
            dtb[d]  = (const float*)d_in[4 + d];
            alog[d] = (const float*)d_in[8 + d];
            Dp[d]   = (const float*)d_in[12 + d];
        }
        WoHF = (const float*)d_in[16]; WoHB = (const float*)d_in[17];
        WoVF = (const float*)d_in[18]; WoVB = (const float*)d_in[19];
        Wout = (const float*)d_in[20];
        v2h  = (const int*)d_in[21];
    }

    float *zxH, *zxV, *ydir, *cat;
    cudaGetSymbolAddress((void**)&zxH,  g_zxH);
    cudaGetSymbolAddress((void**)&zxV,  g_zxV);
    cudaGetSymbolAddress((void**)&ydir, g_ydir);
    cudaGetSymbolAddress((void**)&cat,  g_cat);

    PtrPack pp;
    for (int d = 0; d < 4; d++) {
        pp.q[d]     = dtb[d];
        pp.q[4 + d] = alog[d];
        pp.q[8 + d] = Dp[d];
    }
    k_prep<<<1, 16>>>(pp);

    // Input projections: [16384,256] @ [256,1064] -> padded zx scratch
    k_sgemm<<<dim3(9, Mrows / 128), 256>>>(xH, DMm, WinH, ZXW, ZXW,
                                           zxH, ZXS, ZXS, DMm, 0);
    k_sgemm<<<dim3(9, Mrows / 128), 256>>>(xV, DMm, WinV, ZXW, ZXW,
                                           zxV, ZXS, ZXS, DMm, 0);

    // Chunked linear scan (4 directions fused per launch)
    k_scan1<<<dim3(NCc, Bb * NHh, 4), 64>>>();
    k_scan2<<<32, 64>>>();
    k_scan3<<<dim3(NCc, Bb * NHh, 4), 64>>>(v2h);

    // Per-direction output projections into cat columns.
    // Reference pairing: y_HF@W_out_HB, y_HB@W_out_HF, y_VF@W_out_VB, y_VB@W_out_VF
    const float* Wsel[4] = {WoHB, WoHF, WoVB, WoVF};
    for (int d = 0; d < 4; d++) {
        k_sgemm<<<dim3(2, Mrows / 128), 256>>>(
            ydir + (size_t)d * Bb * Ll * DMm, DMm,
            Wsel[d], DMm, DMm,
            cat + d * DMm, 1024, DMm, DMm, 0);
    }

    // Final: silu(cat) @ W_out -> out
    k_sgemm<<<dim3(2, Mrows / 128), 256>>>(cat, 1024, Wout, DMm, DMm,
                                           (float*)d_out, DMm, DMm, 1024, 1);
}

// round 2
// speedup vs baseline: 1.5041x; 1.5041x over previous
#include <cuda_runtime.h>
#include <math.h>

// Problem constants
#define Bb    2
#define Ll    8192
#define DMm   256
#define NHh   4
#define HPp   64
#define NSs   8
#define DPROJ 532          // 2*DIN + 2*NS + NH
#define ZXW   1064         // 2*DPROJ
#define ZXS   1088         // padded row stride for zx scratch
#define Mrows (Bb*Ll)      // 16384
#define LC    64           // scan chunk length
#define NCc   (Ll/LC)      // 128 chunks

// ---------------- scratch (static device memory; no allocations) -------------
__device__ __align__(16) float g_zxH[(size_t)Mrows * ZXS];
__device__ __align__(16) float g_zxV[(size_t)Mrows * ZXS];
__device__ __align__(16) float g_E  [(size_t)4 * Bb * NHh * NCc * HPp * NSs];
__device__ __align__(16) float g_S0 [(size_t)4 * Bb * NHh * NCc * HPp * NSs];
__device__ __align__(16) float g_P  [4 * Bb * NHh * NCc];
__device__ __align__(16) float g_ydir[(size_t)4 * Bb * Ll * DMm];
__device__ __align__(16) float g_cat [(size_t)Mrows * 1024];
__device__ float g_dtb[4][NHh];
__device__ float g_Aco[4][NHh];
__device__ float g_Dv [4][NHh];

// ---------------- helpers ----------------------------------------------------
__device__ __forceinline__ float siluf(float x) { return x / (1.0f + expf(-x)); }
__device__ __forceinline__ float softplusf(float x) {
    return (x > 20.0f) ? x : log1pf(expf(x));
}
__device__ __forceinline__ unsigned tf32b(float x) {
    unsigned u;
    asm("cvt.rna.tf32.f32 %0, %1;" : "=r"(u) : "f"(x));
    return u;
}

struct PtrPack { const float* q[12]; };  // dtb[4], A_log[4], D[4]

__global__ void k_prep(PtrPack pp) {
    int i = threadIdx.x;
    if (i < 16) {
        int d = i >> 2, h = i & 3;
        g_dtb[d][h] = pp.q[d][h];
        g_Aco[d][h] = -expf(pp.q[4 + d][h]);
        g_Dv [d][h] = pp.q[8 + d][h];
    }
}

// ---------------- tf32 tensor-core GEMM --------------------------------------
// C[M,*] = op(A)[M,K] @ W[K,Nw], fp32 accumulate, tf32 inputs.
// Block tile 128x128, BK=16, 256 threads = 8 warps in 4(M) x 2(N) grid,
// warp tile 32x64 via m16n8k8 mma (2 m-frags x 8 n-frags).
// Double-buffered dynamic smem; rows padded to AP=136 floats so fragment
// LDS addresses hit bank (8*q + g) -> conflict-free.
#define AP 136
#define TFMMA_SMEM (2 * 2 * 16 * AP * 4)   // 2 arrays x 2 buffers x 16 x AP floats

#define MMA_TF32(ac, af, bf)                                              \
    asm volatile(                                                          \
        "mma.sync.aligned.m16n8k8.row.col.f32.tf32.tf32.f32 "              \
        "{%0,%1,%2,%3}, {%4,%5,%6,%7}, {%8,%9}, {%0,%1,%2,%3};"            \
        : "+f"(ac[0]), "+f"(ac[1]), "+f"(ac[2]), "+f"(ac[3])               \
        : "r"(af[0]), "r"(af[1]), "r"(af[2]), "r"(af[3]),                  \
          "r"(bf[0]), "r"(bf[1]))

__global__ __launch_bounds__(256, 1) void k_tfmma(
    const float* __restrict__ A, int lda,
    const float* __restrict__ W, int ldw, int Nw,
    float* __restrict__ C, int ldc, int Nstore,
    int K, int siluA)
{
    extern __shared__ float sm[];
    float* As = sm;                    // [2][16][AP]
    float* Ws = sm + 2 * 16 * AP;      // [2][16][AP]

    const int tid  = threadIdx.x;
    const int lane = tid & 31;
    const int warp = tid >> 5;
    const int wm = (warp & 3) * 32;    // warp M offset in tile
    const int wn = (warp >> 2) * 64;   // warp N offset in tile
    const int g = lane >> 2;           // 0..7
    const int q = lane & 3;            // 0..3
    const int m0 = blockIdx.y * 128;
    const int n0 = blockIdx.x * 128;

    float acc[2][8][4];
#pragma unroll
    for (int mi = 0; mi < 2; mi++)
#pragma unroll
        for (int ni = 0; ni < 8; ni++)
#pragma unroll
            for (int r = 0; r < 4; r++) acc[mi][ni][r] = 0.0f;

    float4 va[2], vw[2];

    // --- staging helpers (inlined via macros on indices) ---
    // A: idx = tid + it*256 ; row = idx>>2 (0..127), kk = (idx&3)*4
    // W: idx = tid + it*256 ; k = idx>>5 (0..15), nc = (idx&31)*4
#define LOAD_TILES(k0)                                                        \
    {                                                                         \
        _Pragma("unroll")                                                     \
        for (int it = 0; it < 2; ++it) {                                      \
            int idx = tid + (it << 8);                                        \
            int row = idx >> 2, kk = (idx & 3) << 2;                          \
            va[it] = *(const float4*)(A + (size_t)(m0 + row) * lda + (k0) + kk); \
            int wk = idx >> 5, nc = (idx & 31) << 2;                          \
            int gc = n0 + nc;                                                 \
            float4 wv = make_float4(0.f, 0.f, 0.f, 0.f);                      \
            if (gc < Nw)                                                      \
                wv = *(const float4*)(W + (size_t)((k0) + wk) * ldw + gc);    \
            vw[it] = wv;                                                      \
        }                                                                     \
    }

#define STORE_TILES(buf)                                                      \
    {                                                                         \
        _Pragma("unroll")                                                     \
        for (int it = 0; it < 2; ++it) {                                      \
            int idx = tid + (it << 8);                                        \
            int row = idx >> 2, kk = (idx & 3) << 2;                          \
            float4 av = va[it];                                               \
            if (siluA) {                                                      \
                av.x = siluf(av.x); av.y = siluf(av.y);                       \
                av.z = siluf(av.z); av.w = siluf(av.w);                       \
            }                                                                 \
            float* ap = As + ((buf) * 16 + kk) * AP + row;                    \
            ap[0 * AP] = __uint_as_float(tf32b(av.x));                        \
            ap[1 * AP] = __uint_as_float(tf32b(av.y));                        \
            ap[2 * AP] = __uint_as_float(tf32b(av.z));                        \
            ap[3 * AP] = __uint_as_float(tf32b(av.w));                        \
            int wk = idx >> 5, nc = (idx & 31) << 2;                          \
            float4 wv = vw[it];                                               \
            float4 wt;                                                        \
            wt.x = __uint_as_float(tf32b(wv.x));                              \
            wt.y = __uint_as_float(tf32b(wv.y));                              \
            wt.z = __uint_as_float(tf32b(wv.z));                              \
            wt.w = __uint_as_float(tf32b(wv.w));                              \
            *(float4*)(Ws + ((buf) * 16 + wk) * AP + nc) = wt;                \
        }                                                                     \
    }

    LOAD_TILES(0);
    STORE_TILES(0);
    __syncthreads();

    const int nIter = K >> 4;
    for (int itk = 0; itk < nIter; ++itk) {
        const int buf = itk & 1;
        if (itk + 1 < nIter) LOAD_TILES((itk + 1) << 4);

#pragma unroll
        for (int kg = 0; kg < 2; ++kg) {
            const float* Ab = As + (buf * 16 + kg * 8 + q) * AP;
            const float* Bb_ = Ws + (buf * 16 + kg * 8 + q) * AP;
            unsigned af[2][4];
#pragma unroll
            for (int mi = 0; mi < 2; mi++) {
                int row = wm + mi * 16 + g;
                af[mi][0] = __float_as_uint(Ab[row]);
                af[mi][1] = __float_as_uint(Ab[row + 8]);
                af[mi][2] = __float_as_uint(Ab[4 * AP + row]);
                af[mi][3] = __float_as_uint(Ab[4 * AP + row + 8]);
            }
            unsigned bf[8][2];
#pragma unroll
            for (int ni = 0; ni < 8; ni++) {
                int col = wn + ni * 8 + g;
                bf[ni][0] = __float_as_uint(Bb_[col]);
                bf[ni][1] = __float_as_uint(Bb_[4 * AP + col]);
            }
#pragma unroll
            for (int mi = 0; mi < 2; mi++)
#pragma unroll
                for (int ni = 0; ni < 8; ni++)
                    MMA_TF32(acc[mi][ni], af[mi], bf[ni]);
        }

        if (itk + 1 < nIter) STORE_TILES(buf ^ 1);
        __syncthreads();
    }

    // Epilogue: c0,c1 at (row, q*2), c2,c3 at (row+8, q*2)
#pragma unroll
    for (int mi = 0; mi < 2; mi++) {
        int row = m0 + wm + mi * 16 + g;
#pragma unroll
        for (int ni = 0; ni < 8; ni++) {
            int col = n0 + wn + ni * 8 + q * 2;
            if (col < Nstore) {
                float2 v0 = make_float2(acc[mi][ni][0], acc[mi][ni][1]);
                float2 v1 = make_float2(acc[mi][ni][2], acc[mi][ni][3]);
                *(float2*)(C + (size_t)row * ldc + col) = v0;
                *(float2*)(C + (size_t)(row + 8) * ldc + col) = v1;
            }
        }
    }
}

// ---------------- scan pass 1: per-chunk local scan from zero state ----------
__global__ __launch_bounds__(64) void k_scan1() {
    const int c  = blockIdx.x;
    const int b  = blockIdx.y >> 2;
    const int h  = blockIdx.y & 3;
    const int d  = blockIdx.z;
    const int p  = threadIdx.x;
    const float* zx = (d < 2) ? g_zxH : g_zxV;
    const int off = (d & 1) * DPROJ;
    const int rev = d & 1;

    __shared__ float sa[LC];
    __shared__ float sdtB[LC][NSs];
    __shared__ float sx[LC][HPp];

    {
        int i = p;
        int t = rev ? (Ll - 1 - (c * LC + i)) : (c * LC + i);
        const float* row = zx + (size_t)(b * Ll + t) * ZXS + off;
        float dt = softplusf(row[528 + h] + g_dtb[d][h]);
        sa[i] = expf(dt * g_Aco[d][h]);
#pragma unroll
        for (int n = 0; n < NSs; n++) sdtB[i][n] = dt * siluf(row[512 + n]);
    }
#pragma unroll 8
    for (int i = 0; i < LC; i++) {
        int t = rev ? (Ll - 1 - (c * LC + i)) : (c * LC + i);
        sx[i][p] = siluf(zx[(size_t)(b * Ll + t) * ZXS + off + 256 + h * HPp + p]);
    }
    __syncthreads();

    float s[NSs];
#pragma unroll
    for (int n = 0; n < NSs; n++) s[n] = 0.0f;
    float pr = 1.0f;
#pragma unroll 4
    for (int i = 0; i < LC; i++) {
        float a = sa[i];
        float xv = sx[i][p];
        pr *= a;
#pragma unroll
        for (int n = 0; n < NSs; n++) s[n] = fmaf(a, s[n], sdtB[i][n] * xv);
    }
    size_t base = ((((size_t)d * Bb + b) * NHh + h) * NCc + c);
    float* Ep = g_E + base * HPp * NSs + p * NSs;
#pragma unroll
    for (int n = 0; n < NSs; n++) Ep[n] = s[n];
    if (p == 0) g_P[base] = pr;
}

// ---------------- scan pass 2: combine chunk summaries -----------------------
__global__ __launch_bounds__(64) void k_scan2() {
    const int bid = blockIdx.x;      // 32 blocks: d*8 + b*4 + h
    const int d = bid >> 3, b = (bid >> 2) & 1, h = bid & 3;
    const int p = threadIdx.x;
    size_t base = (((size_t)d * Bb + b) * NHh + h) * NCc;
    float s[NSs];
#pragma unroll
    for (int n = 0; n < NSs; n++) s[n] = 0.0f;
    for (int c = 0; c < NCc; c++) {
        float* S0p = g_S0 + (base + c) * HPp * NSs + p * NSs;
        const float* Ep = g_E + (base + c) * HPp * NSs + p * NSs;
        float P = g_P[base + c];
#pragma unroll
        for (int n = 0; n < NSs; n++) {
            S0p[n] = s[n];
            s[n] = fmaf(P, s[n], Ep[n]);
        }
    }
}

// ---------------- scan pass 3: replay with true init state, emit y -----------
__global__ __launch_bounds__(64) void k_scan3(const int* __restrict__ v2h) {
    const int c  = blockIdx.x;
    const int b  = blockIdx.y >> 2;
    const int h  = blockIdx.y & 3;
    const int d  = blockIdx.z;
    const int p  = threadIdx.x;
    const float* zx = (d < 2) ? g_zxH : g_zxV;
    const int off = (d & 1) * DPROJ;
    const int rev = d & 1;

    __shared__ float sa[LC];
    __shared__ float sdtB[LC][NSs];
    __shared__ float sC[LC][NSs];
    __shared__ float sx[LC][HPp];
    __shared__ float sz[LC][HPp];

    {
        int i = p;
        int t = rev ? (Ll - 1 - (c * LC + i)) : (c * LC + i);
        const float* row = zx + (size_t)(b * Ll + t) * ZXS + off;
        float dt = softplusf(row[528 + h] + g_dtb[d][h]);
        sa[i] = expf(dt * g_Aco[d][h]);
#pragma unroll
        for (int n = 0; n < NSs; n++) {
            sdtB[i][n] = dt * siluf(row[512 + n]);
            sC[i][n]   = siluf(row[520 + n]);
        }
    }
#pragma unroll 8
    for (int i = 0; i < LC; i++) {
        int t = rev ? (Ll - 1 - (c * LC + i)) : (c * LC + i);
        const float* row = zx + (size_t)(b * Ll + t) * ZXS + off;
        sx[i][p] = siluf(row[256 + h * HPp + p]);
        sz[i][p] = row[h * HPp + p];
    }
    __syncthreads();

    size_t base = ((((size_t)d * Bb + b) * NHh + h) * NCc + c);
    const float* S0p = g_S0 + base * HPp * NSs + p * NSs;
    float s[NSs];
#pragma unroll
    for (int n = 0; n < NSs; n++) s[n] = S0p[n];
    const float Dh = g_Dv[d][h];
    const size_t ybase = (((size_t)d * Bb + b) * Ll);

    for (int i = 0; i < LC; i++) {
        int t = rev ? (Ll - 1 - (c * LC + i)) : (c * LC + i);
        float a = sa[i];
        float xv = sx[i][p];
#pragma unroll
        for (int n = 0; n < NSs; n++) s[n] = fmaf(a, s[n], sdtB[i][n] * xv);
        float y = 0.0f;
#pragma unroll
        for (int n = 0; n < NSs; n++) y = fmaf(s[n], sC[i][n], y);
        float out = (y + Dh * xv) * siluf(sz[i][p]);
        int trow = (d >= 2) ? v2h[b * Ll + t] : t;
        g_ydir[(ybase + trow) * DMm + h * HPp + p] = out;
    }
}

// ---------------- launch -----------------------------------------------------
extern "C" void kernel_launch(void* const* d_in, const int* in_sizes, int n_in,
                              void* d_out, int out_size) {
    const float *xH, *xV, *WinH, *WinV, *WoHF, *WoHB, *WoVF, *WoVB, *Wout;
    const float *dtb[4], *alog[4], *Dp[4];
    const int* v2h;

    if (in_sizes[4] > 1000) {
        // dict (setup_inputs insertion) order
        xH   = (const float*)d_in[0];  xV   = (const float*)d_in[1];
        WinH = (const float*)d_in[2];  WinV = (const float*)d_in[3];
        WoHF = (const float*)d_in[4];  WoHB = (const float*)d_in[5];
        WoVF = (const float*)d_in[6];  WoVB = (const float*)d_in[7];
        Wout = (const float*)d_in[8];
        for (int d = 0; d < 4; d++) {
            dtb[d]  = (const float*)d_in[9 + 3 * d];
            alog[d] = (const float*)d_in[10 + 3 * d];
            Dp[d]   = (const float*)d_in[11 + 3 * d];
        }
        v2h = (const int*)d_in[21];
    } else {
        // reference-signature order
        xH   = (const float*)d_in[0];  xV   = (const float*)d_in[1];
        WinH = (const float*)d_in[2];  WinV = (const float*)d_in[3];
        for (int d = 0; d < 4; d++) {
            dtb[d]  = (const float*)d_in[4 + d];
            alog[d] = (const float*)d_in[8 + d];
            Dp[d]   = (const float*)d_in[12 + d];
        }
        WoHF = (const float*)d_in[16]; WoHB = (const float*)d_in[17];
        WoVF = (const float*)d_in[18]; WoVB = (const float*)d_in[19];
        Wout = (const float*)d_in[20];
        v2h  = (const int*)d_in[21];
    }

    float *zxH, *zxV, *ydir, *cat;
    cudaGetSymbolAddress((void**)&zxH,  g_zxH);
    cudaGetSymbolAddress((void**)&zxV,  g_zxV);
    cudaGetSymbolAddress((void**)&ydir, g_ydir);
    cudaGetSymbolAddress((void**)&cat,  g_cat);

    static int smem_set = 0;
    if (!smem_set) {
        cudaFuncSetAttribute(k_tfmma, cudaFuncAttributeMaxDynamicSharedMemorySize,
                             TFMMA_SMEM);
        smem_set = 1;
    }

    PtrPack pp;
    for (int d = 0; d < 4; d++) {
        pp.q[d]     = dtb[d];
        pp.q[4 + d] = alog[d];
        pp.q[8 + d] = Dp[d];
    }
    k_prep<<<1, 16>>>(pp);

    // Input projections: [16384,256] @ [256,1064] -> padded zx scratch
    k_tfmma<<<dim3(9, Mrows / 128), 256, TFMMA_SMEM>>>(
        xH, DMm, WinH, ZXW, ZXW, zxH, ZXS, ZXS, DMm, 0);
    k_tfmma<<<dim3(9, Mrows / 128), 256, TFMMA_SMEM>>>(
        xV, DMm, WinV, ZXW, ZXW, zxV, ZXS, ZXS, DMm, 0);

    // Chunked linear scan (4 directions fused per launch)
    k_scan1<<<dim3(NCc, Bb * NHh, 4), 64>>>();
    k_scan2<<<32, 64>>>();
    k_scan3<<<dim3(NCc, Bb * NHh, 4), 64>>>(v2h);

    // Per-direction output projections into cat columns.
    // Reference pairing: y_HF@W_out_HB, y_HB@W_out_HF, y_VF@W_out_VB, y_VB@W_out_VF
    const float* Wsel[4] = {WoHB, WoHF, WoVB, WoVF};
    for (int d = 0; d < 4; d++) {
        k_tfmma<<<dim3(2, Mrows / 128), 256, TFMMA_SMEM>>>(
            ydir + (size_t)d * Bb * Ll * DMm, DMm,
            Wsel[d], DMm, DMm,
            cat + d * DMm, 1024, DMm, DMm, 0);
    }

    // Final: silu(cat) @ W_out -> out
    k_tfmma<<<dim3(2, Mrows / 128), 256, TFMMA_SMEM>>>(
        cat, 1024, Wout, DMm, DMm, (float*)d_out, DMm, DMm, 1024, 1);
}